// round 17
// baseline (speedup 1.0000x reference)
#include <cuda_runtime.h>
#include <cuda_bf16.h>
#include <math.h>

#define BB 64
#define TT 101
#define TS 100
#define VV 8000
#define HH 512
#define GG 2048
#define MM (TS*BB)   // 6400
#define EPSN 1e-5f

typedef unsigned long long ull;

// ---------------- device scratch (static; no runtime allocation) -------------
__device__ float g_Xg1[(size_t)GG*MM];           // [t][n][b] e@Wih1^T + b1
__device__ float g_Hout[MM*HH];                  // [m][h] layer-3 output
__device__ float g_logits[(size_t)MM*VV];        // [m][v]
__device__ float g_part[(size_t)2*3*4*GG*BB];    // [parity][layer][slice][n][b]
__device__ float g_c[3*HH*BB];                   // [layer][j][b] cell state
__device__ unsigned g_cnt[3];                    // cumulative gemm completions per layer
__device__ unsigned g_ccnt[3];                   // cumulative cell hd completions per layer
__device__ unsigned g_hcnt[3];                   // cumulative cell h completions (early)
// bf16 split weights: 0:Whh1 1:Wih2 2:Whh2 3:Wih3 4:Whh3 5:Wih1, [slot][n][k]
__device__ __align__(16) __nv_bfloat16 g_WspHi[(size_t)6*GG*HH];
__device__ __align__(16) __nv_bfloat16 g_WspLo[(size_t)6*GG*HH];
// bf16 split activations, parity double-buffered: [parity][layer][b][k]
__device__ __align__(16) __nv_bfloat16 g_hbfHi[2*3*BB*HH];
__device__ __align__(16) __nv_bfloat16 g_hbfLo[2*3*BB*HH];
__device__ __align__(16) __nv_bfloat16 g_hdbfHi[2*2*BB*HH];
__device__ __align__(16) __nv_bfloat16 g_hdbfLo[2*2*BB*HH];
// bf16 split embeddings, [m][k]
__device__ __align__(16) __nv_bfloat16 g_ebfHi[(size_t)MM*HH];
__device__ __align__(16) __nv_bfloat16 g_ebfLo[(size_t)MM*HH];

// ---------------- helpers ------------------------------------------------------
__device__ __forceinline__ unsigned tf32c(float x) {
    unsigned u;
    asm("cvt.rna.tf32.f32 %0, %1;" : "=r"(u) : "f"(x));
    return u;
}
__device__ __forceinline__ void mma_tf32(float* c, const unsigned* a, const unsigned* b) {
    asm("mma.sync.aligned.m16n8k8.row.col.f32.tf32.tf32.f32 "
        "{%0,%1,%2,%3}, {%4,%5,%6,%7}, {%8,%9}, {%0,%1,%2,%3};"
        : "+f"(c[0]), "+f"(c[1]), "+f"(c[2]), "+f"(c[3])
        : "r"(a[0]), "r"(a[1]), "r"(a[2]), "r"(a[3]), "r"(b[0]), "r"(b[1]));
}
__device__ __forceinline__ void mma_bf16(float* c, const unsigned* a, const unsigned* b) {
    asm("mma.sync.aligned.m16n8k16.row.col.f32.bf16.bf16.f32 "
        "{%0,%1,%2,%3}, {%4,%5,%6,%7}, {%8,%9}, {%0,%1,%2,%3};"
        : "+f"(c[0]), "+f"(c[1]), "+f"(c[2]), "+f"(c[3])
        : "r"(a[0]), "r"(a[1]), "r"(a[2]), "r"(a[3]), "r"(b[0]), "r"(b[1]));
}
__device__ __forceinline__ void ldsm4(unsigned* r, unsigned addr) {
    asm volatile("ldmatrix.sync.aligned.m8n8.x4.shared.b16 {%0,%1,%2,%3}, [%4];"
                 : "=r"(r[0]), "=r"(r[1]), "=r"(r[2]), "=r"(r[3]) : "r"(addr));
}
__device__ __forceinline__ void bsplit(float x, __nv_bfloat16& hi, __nv_bfloat16& lo) {
    hi = __float2bfloat16(x);
    lo = __float2bfloat16(x - __bfloat162float(hi));
}
__device__ __forceinline__ void cpa16(unsigned dst, const void* src) {
    asm volatile("cp.async.ca.shared.global [%0], [%1], 16;" :: "r"(dst), "l"(src));
}
__device__ __forceinline__ void cpa16cg(unsigned dst, const void* src) {
    asm volatile("cp.async.cg.shared.global [%0], [%1], 16;" :: "r"(dst), "l"(src));
}
__device__ __forceinline__ void waitCnt(unsigned* addr, unsigned tgt) {
    unsigned v;
    int spins = 0;
    while (true) {
        asm volatile("ld.acquire.gpu.u32 %0, [%1];" : "=r"(v) : "l"(addr) : "memory");
        if (v >= tgt) break;
        if (++spins > 64) __nanosleep(64);
    }
}
__device__ __forceinline__ int iclamp(int x, int lo, int hi) {
    return x < lo ? lo : (x > hi ? hi : x);
}
__device__ __forceinline__ float fsig(float x) {
    return 1.f / (1.f + __expf(-x));
}
__device__ __forceinline__ float ftanh(float x) {
    float xc = fminf(fmaxf(x, -15.f), 15.f);
    float e = __expf(2.f * xc);
    return __fdividef(e - 1.f, e + 1.f);
}

// ---------------- init: zero states + counters + loss slot --------------------
__global__ void k_init(float* out, int hasLoss) {
    int i = blockIdx.x * blockDim.x + threadIdx.x;
    if (i < 3*HH*BB) g_c[i] = 0.f;
    if (i < 2*3*BB*HH) {
        g_hbfHi[i] = __float2bfloat16(0.f);
        g_hbfLo[i] = __float2bfloat16(0.f);
    }
    if (i < 3) { g_cnt[i] = 0u; g_ccnt[i] = 0u; g_hcnt[i] = 0u; }
    if (i == 0 && hasLoss) out[0] = 0.f;
}

// ---------------- weight pre-split (once): 6 matrices [2048][512] ------------
__global__ void k_wsplit(const float* __restrict__ Whh1,
                         const float* __restrict__ Wih2, const float* __restrict__ Whh2,
                         const float* __restrict__ Wih3, const float* __restrict__ Whh3,
                         const float* __restrict__ Wih1) {
    int i = blockIdx.x * blockDim.x + threadIdx.x;   // float4 index
    const int PER = GG * (HH/4);
    if (i >= 6 * PER) return;
    int slot = i / PER, rem = i - slot * PER;
    const float* M = slot == 0 ? Whh1 : slot == 1 ? Wih2 : slot == 2 ? Whh2
                   : slot == 3 ? Wih3 : slot == 4 ? Whh3 : Wih1;
    float4 v = ((const float4*)M)[rem];
    __nv_bfloat16 h0,l0,h1,l1,h2,l2,h3,l3;
    bsplit(v.x, h0, l0); bsplit(v.y, h1, l1);
    bsplit(v.z, h2, l2); bsplit(v.w, h3, l3);
    size_t o = (size_t)slot*GG*HH + (size_t)rem*4;
    *(__nv_bfloat162*)&g_WspHi[o]   = __nv_bfloat162(h0, h1);
    *(__nv_bfloat162*)&g_WspHi[o+2] = __nv_bfloat162(h2, h3);
    *(__nv_bfloat162*)&g_WspLo[o]   = __nv_bfloat162(l0, l1);
    *(__nv_bfloat162*)&g_WspLo[o+2] = __nv_bfloat162(l2, l3);
}

// ---------------- embedding gather + bf16 split -------------------------------
__global__ void k_embed(const int* x, const float* emb) {
    int i = blockIdx.x * blockDim.x + threadIdx.x;
    if (i >= MM * (HH/4)) return;
    int m  = i / (HH/4);
    int hq = i % (HH/4);
    int t = m / BB, b = m % BB;
    int tok = x[b*TT + t];
    float4 v = ((const float4*)emb)[(size_t)tok*(HH/4) + hq];
    __nv_bfloat16 h0,l0,h1,l1,h2,l2,h3,l3;
    bsplit(v.x, h0, l0); bsplit(v.y, h1, l1);
    bsplit(v.z, h2, l2); bsplit(v.w, h3, l3);
    size_t o = (size_t)m*HH + (size_t)hq*4;
    *(__nv_bfloat162*)&g_ebfHi[o]   = __nv_bfloat162(h0, h1);
    *(__nv_bfloat162*)&g_ebfHi[o+2] = __nv_bfloat162(h2, h3);
    *(__nv_bfloat162*)&g_ebfLo[o]   = __nv_bfloat162(l0, l1);
    *(__nv_bfloat162*)&g_ebfLo[o+2] = __nv_bfloat162(l2, l3);
}

// ---------------- Xg1 GEMM: bf16 split-3 tensor cores -------------------------
__global__ void __launch_bounds__(256) k_xg1_tc(const float* __restrict__ bias) {
    int t = blockIdx.y;
    int nb = blockIdx.x * 128;
    const __nv_bfloat16* wHi = g_WspHi + ((size_t)5*GG + nb)*HH;
    const __nv_bfloat16* wLo = g_WspLo + ((size_t)5*GG + nb)*HH;
    const __nv_bfloat16* aHi = g_ebfHi + (size_t)t*BB*HH;
    const __nv_bfloat16* aLo = g_ebfLo + (size_t)t*BB*HH;

    int tid = threadIdx.x;
    int lane = tid & 31, warp = tid >> 5;
    int mwarp = warp >> 1, bwarp = warp & 1;

    __shared__ __align__(16) __nv_bfloat16 sWhi[128*40];
    __shared__ __align__(16) __nv_bfloat16 sWlo[128*40];
    __shared__ __align__(16) __nv_bfloat16 sAhi[64*40];
    __shared__ __align__(16) __nv_bfloat16 sAlo[64*40];
    unsigned bWhi = (unsigned)__cvta_generic_to_shared(sWhi);
    unsigned bWlo = (unsigned)__cvta_generic_to_shared(sWlo);
    unsigned bAhi = (unsigned)__cvta_generic_to_shared(sAhi);
    unsigned bAlo = (unsigned)__cvta_generic_to_shared(sAlo);

    float acc[2][4][4];
#pragma unroll
    for (int mt = 0; mt < 2; mt++)
#pragma unroll
        for (int j = 0; j < 4; j++)
#pragma unroll
            for (int e = 0; e < 4; e++) acc[mt][j][e] = 0.f;

    int aRow = mwarp*32 + (lane & 15);
    int aColHalf = (lane >> 4) * 16;
    int bSel = lane >> 3, bL = lane & 7;
    int bRowOff = (bSel >> 1) * 8 + bL;
    int bColHalf = (bSel & 1) * 16;

    int wr0 = tid >> 1, wc0 = (tid & 1) * 2;
    int ar = tid >> 2, ac = tid & 3;

    for (int kc = 0; kc < HH; kc += 32) {
#pragma unroll
        for (int u = 0; u < 2; u++) {
            int r = wr0, c = wc0 + u;
            cpa16(bWhi + r*80 + c*16, wHi + (size_t)r*HH + kc + c*8);
            cpa16(bWlo + r*80 + c*16, wLo + (size_t)r*HH + kc + c*8);
        }
        cpa16(bAhi + ar*80 + ac*16, aHi + (size_t)ar*HH + kc + ac*8);
        cpa16(bAlo + ar*80 + ac*16, aLo + (size_t)ar*HH + kc + ac*8);
        asm volatile("cp.async.commit_group;");
        asm volatile("cp.async.wait_group 0;");
        __syncthreads();

#pragma unroll
        for (int kq = 0; kq < 2; kq++) {
            unsigned wa_h[2][4], wa_l[2][4];
#pragma unroll
            for (int mt = 0; mt < 2; mt++) {
                unsigned off = (unsigned)((aRow + mt*16)*80 + kq*32 + aColHalf);
                ldsm4(wa_h[mt], bWhi + off);
                ldsm4(wa_l[mt], bWlo + off);
            }
            unsigned hb_h[4][2], hb_l[4][2];
#pragma unroll
            for (int j2 = 0; j2 < 2; j2++) {
                unsigned off = (unsigned)((bwarp*32 + j2*16 + bRowOff)*80 + kq*32 + bColHalf);
                unsigned q[4];
                ldsm4(q, bAhi + off);
                hb_h[2*j2][0] = q[0]; hb_h[2*j2][1] = q[1];
                hb_h[2*j2+1][0] = q[2]; hb_h[2*j2+1][1] = q[3];
                ldsm4(q, bAlo + off);
                hb_l[2*j2][0] = q[0]; hb_l[2*j2][1] = q[1];
                hb_l[2*j2+1][0] = q[2]; hb_l[2*j2+1][1] = q[3];
            }
#pragma unroll
            for (int mt = 0; mt < 2; mt++)
#pragma unroll
                for (int j = 0; j < 4; j++) {
                    mma_bf16(acc[mt][j], wa_h[mt], hb_h[j]);
                    mma_bf16(acc[mt][j], wa_h[mt], hb_l[j]);
                    mma_bf16(acc[mt][j], wa_l[mt], hb_h[j]);
                }
        }
        __syncthreads();
    }

    float* P = g_Xg1 + (size_t)t*(GG*BB) + (size_t)nb*BB;
    int g = lane >> 2, tg = lane & 3;
#pragma unroll
    for (int mt = 0; mt < 2; mt++) {
        int n = mwarp*32 + mt*16 + g;
        float bb0 = bias[nb + n], bb1 = bias[nb + n + 8];
#pragma unroll
        for (int j = 0; j < 4; j++) {
            int b = bwarp*32 + j*8 + 2*tg;
            float2 v0; v0.x = acc[mt][j][0] + bb0; v0.y = acc[mt][j][1] + bb0;
            float2 v1; v1.x = acc[mt][j][2] + bb1; v1.y = acc[mt][j][3] + bb1;
            *(float2*)&P[(size_t)n*BB + b]       = v0;
            *(float2*)&P[(size_t)(n + 8)*BB + b] = v1;
        }
    }
}

// ---------------- decoder GEMM: TF32 tensor cores -----------------------------
__global__ void __launch_bounds__(256) k_dec_tc(const float* __restrict__ Wd,
                                                const float* __restrict__ bd) {
    __shared__ unsigned Ast[32*136];
    __shared__ unsigned Bst[32*136];
    int tid = threadIdx.x;
    int warp = tid >> 5, lane = tid & 31;
    int gid = lane >> 2, tig = lane & 3;
    int mBase = blockIdx.y * 128, nBase = blockIdx.x * 128;
    int wm = (warp >> 2) * 64, wn = (warp & 3) * 32;

    float c[4][4][4];
#pragma unroll
    for (int i = 0; i < 4; i++)
#pragma unroll
        for (int j = 0; j < 4; j++)
#pragma unroll
            for (int e = 0; e < 4; e++) c[i][j][e] = 0.f;

    int srow = tid & 127;
    int half = tid >> 7;
    int nIdx = nBase + srow;
    bool nOk = nIdx < VV;
    const float* aRow = &g_Hout[(size_t)(mBase + srow)*HH];
    const float* bRow = &Wd[(size_t)(nOk ? nIdx : 0)*HH];

    for (int kc = 0; kc < HH; kc += 32) {
        float4 av[4], bv[4];
#pragma unroll
        for (int i = 0; i < 4; i++) {
            av[i] = *(const float4*)&aRow[kc + half*16 + i*4];
            float4 b = *(const float4*)&bRow[kc + half*16 + i*4];
            if (!nOk) b = make_float4(0.f, 0.f, 0.f, 0.f);
            bv[i] = b;
        }
        __syncthreads();
#pragma unroll
        for (int i = 0; i < 4; i++) {
            int k = half*16 + i*4;
            Ast[(k+0)*136 + srow] = tf32c(av[i].x);
            Ast[(k+1)*136 + srow] = tf32c(av[i].y);
            Ast[(k+2)*136 + srow] = tf32c(av[i].z);
            Ast[(k+3)*136 + srow] = tf32c(av[i].w);
            Bst[(k+0)*136 + srow] = tf32c(bv[i].x);
            Bst[(k+1)*136 + srow] = tf32c(bv[i].y);
            Bst[(k+2)*136 + srow] = tf32c(bv[i].z);
            Bst[(k+3)*136 + srow] = tf32c(bv[i].w);
        }
        __syncthreads();
#pragma unroll
        for (int ks = 0; ks < 32; ks += 8) {
            unsigned a[4][4], b[4][2];
            int r0 = (ks + tig)*136, r1 = (ks + tig + 4)*136;
#pragma unroll
            for (int i = 0; i < 4; i++) {
                int mo = wm + i*16 + gid;
                a[i][0] = Ast[r0 + mo]; a[i][1] = Ast[r0 + mo + 8];
                a[i][2] = Ast[r1 + mo]; a[i][3] = Ast[r1 + mo + 8];
            }
#pragma unroll
            for (int j = 0; j < 4; j++) {
                int no = wn + j*8 + gid;
                b[j][0] = Bst[r0 + no];
                b[j][1] = Bst[r1 + no];
            }
#pragma unroll
            for (int i = 0; i < 4; i++)
#pragma unroll
                for (int j = 0; j < 4; j++)
                    mma_tf32(c[i][j], a[i], b[j]);
        }
    }

#pragma unroll
    for (int i = 0; i < 4; i++) {
        int r0 = mBase + wm + i*16 + gid;
#pragma unroll
        for (int j = 0; j < 4; j++) {
            int n = nBase + wn + j*8 + 2*tig;
            if (n < VV) {
                float2 bb = *(const float2*)&bd[n];
                float2 v0; v0.x = c[i][j][0] + bb.x; v0.y = c[i][j][1] + bb.y;
                float2 v1; v1.x = c[i][j][2] + bb.x; v1.y = c[i][j][3] + bb.y;
                *(float2*)&g_logits[(size_t)r0*VV + n]       = v0;
                *(float2*)&g_logits[(size_t)(r0 + 8)*VV + n] = v1;
            }
        }
    }
}

// ---------------- PERSISTENT wavefront: 128 CTAs x 512 thr, 1 CTA/SM ----------
// CTAs 0..79 = gemm role (256n x 64b x 256k, two 128n halves, full-SM tensor
// pipe). CTAs 80..127 = cell role (32 j x 64 b each). Same lockstep counter
// protocol as R16, counts rescaled: gemm/layer = 16 (l0) / 32; cell/layer = 16.
__global__ void __launch_bounds__(512, 1) k_persist_wave(
    const float* __restrict__ b2, const float* __restrict__ b3,
    const float* __restrict__ gm0, const float* __restrict__ bt0, const float* __restrict__ mk0,
    const float* __restrict__ gm1, const float* __restrict__ bt1, const float* __restrict__ mk1,
    const float* __restrict__ gm2, const float* __restrict__ bt2, const float* __restrict__ mk2)
{
    extern __shared__ __align__(16) __nv_bfloat16 smemRaw[];
    int bx = blockIdx.x;
    int tid = threadIdx.x;

    if (bx < 80) {
        // =================== GEMM role ===================
        int l, ntp, slice;
        if (bx < 16)      { l = 0; ntp = bx & 7;        slice = bx >> 3; }
        else if (bx < 48) { l = 1; ntp = (bx-16) & 7;   slice = (bx-16) >> 3; }
        else              { l = 2; ntp = (bx-48) & 7;   slice = (bx-48) >> 3; }

        int wslot, kOff;
        int useH;   // 1: reads g_hbf[l]; 0: reads g_hdbf[l-1]
        if (l == 0)          { wslot = 0;       kOff = slice * 256;       useH = 1; }
        else if (slice < 2)  { wslot = 2*l - 1; kOff = slice * 256;       useH = 0; }
        else                 { wslot = 2*l;     kOff = (slice - 2) * 256; useH = 1; }

        int half = tid >> 8, tl = tid & 255;
        int nb = ntp * 256 + half * 128;           // this half's 128n base
        const __nv_bfloat16* wHi = g_WspHi + ((size_t)wslot*GG + nb)*HH + kOff;
        const __nv_bfloat16* wLo = g_WspLo + ((size_t)wslot*GG + nb)*HH + kOff;

        unsigned smemB = (unsigned)__cvta_generic_to_shared(smemRaw);
        unsigned bWhi = smemB + half*20480u;            // [stage][128r x 80B]
        unsigned bWlo = smemB + 40960u + half*20480u;
        unsigned bAhi = smemB + 81920u;
        unsigned bAlo = smemB + 92160u;

        int lane = tid & 31, warp = tid >> 5;
        int w8 = warp & 7;
        int mwarp = w8 >> 1, bwarp = w8 & 1;
        int aRow = mwarp*32 + (lane & 15);
        int aColHalf = (lane >> 4) * 16;
        int bSel = lane >> 3, bL = lane & 7;
        int bRowOff = (bSel >> 1) * 8 + bL;
        int bColHalf = (bSel & 1) * 16;
        int wr0 = tl >> 1, wc0 = (tl & 1) * 2;
        int ar = tl >> 2, ac = tl & 3;

        for (int d = l; d < l + TS; d++) {
            // ---- prefetch chunk-0 weights BEFORE the wait (weights static) ----
#pragma unroll
            for (int u = 0; u < 2; u++) {
                int c = wc0 + u;
                cpa16(bWhi + wr0*80 + c*16, wHi + (size_t)wr0*HH + c*8);
                cpa16(bWlo + wr0*80 + c*16, wLo + (size_t)wr0*HH + c*8);
            }
            // ---- waits: activation producers (lockstep gates) ----
            if (tid == 0) {
                if (useH) {
                    waitCnt(&g_hcnt[l], 16u * (unsigned)iclamp(d - l, 0, TS));
                } else {
                    waitCnt(&g_ccnt[l-1], 16u * (unsigned)iclamp(d - l + 1, 0, TS));
                    waitCnt(&g_hcnt[l],   16u * (unsigned)iclamp(d - l, 0, TS));
                }
            }
            __syncthreads();

            int pr = (d + 1) & 1;   // read parity = (d-1)&1
            const __nv_bfloat16 *aHi, *aLo;
            if (useH) {
                aHi = g_hbfHi + ((size_t)pr*3 + l)*BB*HH + kOff;
                aLo = g_hbfLo + ((size_t)pr*3 + l)*BB*HH + kOff;
            } else {
                aHi = g_hdbfHi + ((size_t)pr*2 + (l-1))*BB*HH + kOff;
                aLo = g_hdbfLo + ((size_t)pr*2 + (l-1))*BB*HH + kOff;
            }

            float acc[2][4][4];
#pragma unroll
            for (int mt = 0; mt < 2; mt++)
#pragma unroll
                for (int j = 0; j < 4; j++)
#pragma unroll
                    for (int e = 0; e < 4; e++) acc[mt][j][e] = 0.f;

            // stage chunk-0 A; commit joins the pre-issued W of chunk 0
            if (half == 0) cpa16cg(bAhi + ar*80 + ac*16, aHi + (size_t)ar*HH + ac*8);
            else           cpa16cg(bAlo + ar*80 + ac*16, aLo + (size_t)ar*HH + ac*8);
            asm volatile("cp.async.commit_group;");

            for (int ch = 0; ch < 8; ch++) {
                if (ch + 1 < 8) {
                    int kc = (ch + 1) * 32;
                    int st = (ch + 1) & 1;
                    unsigned oW = st * 10240u, oA = st * 5120u;
#pragma unroll
                    for (int u = 0; u < 2; u++) {
                        int c = wc0 + u;
                        cpa16(bWhi + oW + wr0*80 + c*16, wHi + (size_t)wr0*HH + kc + c*8);
                        cpa16(bWlo + oW + wr0*80 + c*16, wLo + (size_t)wr0*HH + kc + c*8);
                    }
                    if (half == 0) cpa16cg(bAhi + oA + ar*80 + ac*16, aHi + (size_t)ar*HH + kc + ac*8);
                    else           cpa16cg(bAlo + oA + ar*80 + ac*16, aLo + (size_t)ar*HH + kc + ac*8);
                    asm volatile("cp.async.commit_group;");
                    asm volatile("cp.async.wait_group 1;");
                } else {
                    asm volatile("cp.async.wait_group 0;");
                }
                __syncthreads();

                int st = ch & 1;
                unsigned oW = st * 10240u, oA = st * 5120u;
#pragma unroll
                for (int kq = 0; kq < 2; kq++) {
                    unsigned wa_h[2][4], wa_l[2][4];
#pragma unroll
                    for (int mt = 0; mt < 2; mt++) {
                        unsigned off = (unsigned)((aRow + mt*16)*80 + kq*32 + aColHalf);
                        ldsm4(wa_h[mt], bWhi + oW + off);
                        ldsm4(wa_l[mt], bWlo + oW + off);
                    }
                    unsigned hb_h[4][2], hb_l[4][2];
#pragma unroll
                    for (int j2 = 0; j2 < 2; j2++) {
                        unsigned off = (unsigned)((bwarp*32 + j2*16 + bRowOff)*80 + kq*32 + bColHalf);
                        unsigned q[4];
                        ldsm4(q, bAhi + oA + off);
                        hb_h[2*j2][0] = q[0]; hb_h[2*j2][1] = q[1];
                        hb_h[2*j2+1][0] = q[2]; hb_h[2*j2+1][1] = q[3];
                        ldsm4(q, bAlo + oA + off);
                        hb_l[2*j2][0] = q[0]; hb_l[2*j2][1] = q[1];
                        hb_l[2*j2+1][0] = q[2]; hb_l[2*j2+1][1] = q[3];
                    }
#pragma unroll
                    for (int mt = 0; mt < 2; mt++)
#pragma unroll
                        for (int j = 0; j < 4; j++) {
                            mma_bf16(acc[mt][j], wa_h[mt], hb_h[j]);
                            mma_bf16(acc[mt][j], wa_h[mt], hb_l[j]);
                            mma_bf16(acc[mt][j], wa_l[mt], hb_h[j]);
                        }
                }
                __syncthreads();
            }

            // partial store: parity-buffered
            float* P = g_part + ((size_t)((d & 1)*12 + l*4 + slice)*GG + nb)*BB;
            int g = lane >> 2, tg = lane & 3;
#pragma unroll
            for (int mt = 0; mt < 2; mt++) {
                int n = mwarp*32 + mt*16 + g;
#pragma unroll
                for (int j = 0; j < 4; j++) {
                    int b = bwarp*32 + j*8 + 2*tg;
                    float2 v0; v0.x = acc[mt][j][0]; v0.y = acc[mt][j][1];
                    float2 v1; v1.x = acc[mt][j][2]; v1.y = acc[mt][j][3];
                    *(float2*)&P[(size_t)n*BB + b]       = v0;
                    *(float2*)&P[(size_t)(n + 8)*BB + b] = v1;
                }
            }
            __syncthreads();
            if (tid == 0)
                asm volatile("red.release.gpu.add.u32 [%0], 1;"
                             :: "l"(&g_cnt[l]) : "memory");
        }
        return;
    }

    // =================== CELL role (512 thr: 32 j x 16 bq) ===================
    int idx = bx - 80;
    int l = idx >> 4, jt = idx & 15;
    int jl = tid >> 4, bq = tid & 15;
    int j = jt * 32 + jl;
    int b0 = bq * 4;
    const float* biasP = (l == 1) ? b2 : b3;
    const float* gmP = (l == 0) ? gm0 : (l == 1) ? gm1 : gm2;
    const float* btP = (l == 0) ? bt0 : (l == 1) ? bt1 : bt2;
    const float* mkP = (l == 0) ? mk0 : (l == 1) ? mk1 : mk2;
    unsigned per_l = (l == 0) ? 16u : 32u;
    float* cP = g_c + l*HH*BB + j*BB + b0;
    float mk4[4];
#pragma unroll
    for (int e = 0; e < 4; e++) mk4[e] = mkP[(b0+e)*HH + j];
    float gmv = gmP[j], btv = btP[j];
    float bias4[4];
#pragma unroll
    for (int g = 0; g < 4; g++) bias4[g] = (l == 0) ? 0.f : biasP[(g << 9) + j];

    for (int d = l; d < l + TS; d++) {
        int t = d - l;
        if (tid == 0)
            waitCnt(&g_cnt[l], per_l * (unsigned)iclamp(d - l + 1, 0, TS));
        __syncthreads();

        float ga[4][4];
#pragma unroll
        for (int g = 0; g < 4; g++) {
            int n = (g << 9) + j;
            float4 s;
            if (l == 0) {
                s = *(const float4*)&g_Xg1[(size_t)t*(GG*BB) + (size_t)n*BB + b0];
            } else {
                float bv = bias4[g];
                s = make_float4(bv, bv, bv, bv);
            }
            const float* pp = g_part + ((size_t)((d & 1)*12 + l*4)*GG + n)*BB + b0;
            int nsl = (l == 0) ? 2 : 4;
            for (int sl = 0; sl < nsl; sl++) {
                float4 v = __ldcg((const float4*)(pp + (size_t)sl*(GG*BB)));
                s.x += v.x; s.y += v.y; s.z += v.z; s.w += v.w;
            }
            ga[g][0] = s.x; ga[g][1] = s.y; ga[g][2] = s.z; ga[g][3] = s.w;
        }

        float4 cprev = *(const float4*)cP;
        float cpv[4] = {cprev.x, cprev.y, cprev.z, cprev.w};
        float hh[4], ccv[4];
#pragma unroll
        for (int e = 0; e < 4; e++) {
            float iv = fsig(ga[0][e]);
            float fv = fsig(ga[1][e]);
            float gv = ftanh(ga[2][e]);
            float ov = fsig(ga[3][e]);
            float cc = fv * cpv[e] + iv * gv;
            ccv[e] = cc;
            hh[e] = ov * ftanh(cc);
        }
        *(float4*)cP = make_float4(ccv[0], ccv[1], ccv[2], ccv[3]);

        int pw = d & 1;
        {
            __nv_bfloat16 hi, lo;
#pragma unroll
            for (int e = 0; e < 4; e++) {
                bsplit(hh[e], hi, lo);
                size_t o = ((size_t)pw*3 + l)*BB*HH + (size_t)(b0+e)*HH + j;
                g_hbfHi[o] = hi;
                g_hbfLo[o] = lo;
            }
        }
        // ---- EARLY h release ----
        __syncthreads();
        if (tid == 0)
            asm volatile("red.release.gpu.add.u32 [%0], 1;"
                         :: "l"(&g_hcnt[l]) : "memory");

        float sum = hh[0] + hh[1] + hh[2] + hh[3];
        float sq  = hh[0]*hh[0] + hh[1]*hh[1] + hh[2]*hh[2] + hh[3]*hh[3];
#pragma unroll
        for (int o = 8; o; o >>= 1) {
            sum += __shfl_down_sync(0xffffffffu, sum, o, 16);
            sq  += __shfl_down_sync(0xffffffffu, sq,  o, 16);
        }
        sum = __shfl_sync(0xffffffffu, sum, 0, 16);
        sq  = __shfl_sync(0xffffffffu, sq,  0, 16);
        float mu  = sum * (1.f / BB);
        float var = sq  * (1.f / BB) - mu * mu;
        float rs  = rsqrtf(var + EPSN);

        if (l < 2) {
            // hd overwrite guard: gemm(d-1, l+1) fully done (32 CTAs/diag)
            if (tid == 0)
                waitCnt(&g_cnt[l+1], 32u * (unsigned)iclamp(d - l, 0, TS));
            __syncthreads();
            __nv_bfloat16 hi, lo;
#pragma unroll
            for (int e = 0; e < 4; e++) {
                float hd = (gmv * (hh[e] - mu) * rs + btv) * mk4[e];
                bsplit(hd, hi, lo);
                size_t o = ((size_t)pw*2 + l)*BB*HH + (size_t)(b0+e)*HH + j;
                g_hdbfHi[o] = hi;
                g_hdbfLo[o] = lo;
            }
            __syncthreads();
            if (tid == 0)
                asm volatile("red.release.gpu.add.u32 [%0], 1;"
                             :: "l"(&g_ccnt[l]) : "memory");
        } else {
#pragma unroll
            for (int e = 0; e < 4; e++) {
                float hd = (gmv * (hh[e] - mu) * rs + btv) * mk4[e];
                g_Hout[((size_t)t*BB + b0 + e)*HH + j] = hd;
            }
        }
    }
}

// ---------------- loss: mean NLL over 6400 rows of 8000 logits --------------
__global__ void k_loss(const int* __restrict__ x, float* out) {
    int r = blockIdx.x;
    int t = r >> 6, b = r & 63;
    const float* row = &g_logits[(size_t)r * VV];
    int tid = threadIdx.x;
    float m = -INFINITY, s = 0.f;
    for (int v = tid; v < VV; v += 256) {
        float xv = row[v];
        if (xv > m) { s = s * expf(m - xv) + 1.f; m = xv; }
        else s += expf(xv - m);
    }
    __shared__ float sm[256], ss[256];
    sm[tid] = m; ss[tid] = s;
    __syncthreads();
    for (int o = 128; o; o >>= 1) {
        if (tid < o) {
            float m2 = sm[tid + o], s2 = ss[tid + o];
            float mm = fmaxf(sm[tid], m2);
            ss[tid] = ss[tid] * expf(sm[tid] - mm) + s2 * expf(m2 - mm);
            sm[tid] = mm;
        }
        __syncthreads();
    }
    if (tid == 0) {
        int tgt = x[b*TT + t + 1];
        float lse = sm[0] + logf(ss[0]);
        atomicAdd(out, (lse - row[tgt]) * (1.f / MM));
    }
}

// ---------------- transpose [t*64+b][v] -> out[b][v][t] ---------------------
__global__ void k_transpose(float* __restrict__ outLogits) {
    int b = blockIdx.x;
    int v0 = blockIdx.y * 32;
    __shared__ float tile[32 * 101];
    int tid = threadIdx.x;
    for (int idx = tid; idx < 3200; idx += 256) {
        int t = idx >> 5, vi = idx & 31;
        tile[vi*101 + t] = g_logits[(size_t)(t*BB + b)*VV + v0 + vi];
    }
    __syncthreads();
    for (int idx = tid; idx < 3200; idx += 256) {
        int vi = idx / 100, t = idx - vi*100;
        outLogits[(size_t)b*VV*TS + (size_t)(v0 + vi)*TS + t] = tile[vi*101 + t];
    }
}

// ---------------- launch ------------------------------------------------------
extern "C" void kernel_launch(void* const* d_in, const int* in_sizes, int n_in,
                              void* d_out, int out_size) {
    const int*   x   = (const int*)d_in[0];
    const float* emb = (const float*)d_in[1];
    const float* Wd  = (const float*)d_in[2];
    const float* bd  = (const float*)d_in[3];
    const float* Wih[3] = {(const float*)d_in[4],  (const float*)d_in[10], (const float*)d_in[16]};
    const float* Whh[3] = {(const float*)d_in[5],  (const float*)d_in[11], (const float*)d_in[17]};
    const float* bl[3]  = {(const float*)d_in[6],  (const float*)d_in[12], (const float*)d_in[18]};
    const float* gm[3]  = {(const float*)d_in[7],  (const float*)d_in[13], (const float*)d_in[19]};
    const float* bt[3]  = {(const float*)d_in[8],  (const float*)d_in[14], (const float*)d_in[20]};
    const float* mk[3]  = {(const float*)d_in[9],  (const float*)d_in[15], (const float*)d_in[21]};

    float* out = (float*)d_out;
    int hasLoss = (out_size & 1) ? 1 : 0;
    float* outLogits = out + hasLoss;

    const int FUSED_SMEM = 102400;   // W(hi/lo) 2 halves x 2 stages + A(hi/lo) x 2 stages
    static int attrDone = 0;
    if (!attrDone) {
        cudaFuncSetAttribute(k_persist_wave, cudaFuncAttributeMaxDynamicSharedMemorySize,
                             FUSED_SMEM);
        attrDone = 1;
    }

    k_init<<<(2*3*HH*BB + 255)/256, 256>>>(out, hasLoss);
    k_wsplit<<<(6*GG*(HH/4) + 255)/256, 256>>>(Whh[0], Wih[1], Whh[1], Wih[2], Whh[2], Wih[0]);
    k_embed<<<(MM*(HH/4) + 255)/256, 256>>>(x, emb);
    k_xg1_tc<<<dim3(16, TS), 256>>>(bl[0]);

    k_persist_wave<<<128, 512, FUSED_SMEM>>>(bl[1], bl[2],
                                             gm[0], bt[0], mk[0],
                                             gm[1], bt[1], mk[1],
                                             gm[2], bt[2], mk[2]);

    k_dec_tc<<<dim3((VV + 127)/128, MM/128), 256>>>(Wd, bd);
    if (hasLoss) k_loss<<<MM, 256>>>(x, out);
    k_transpose<<<dim3(BB, VV/32), 256>>>(outLogits);
}